// round 14
// baseline (speedup 1.0000x reference)
#include <cuda_runtime.h>
#include <math.h>

#define N_NODES 20000
#define D_IN 256
#define H1 128
#define H2 16
#define KG_E 200000
#define SL_E 20000
#define NG 8
#define TOT_EDGES (SL_E + 7 * KG_E)
#define E_CNN 40000
#define CNN_SUBS 5
#define CNN_THREADS (128 * CNN_SUBS)   // 640
#define NB (NG * N_NODES)              // 160000 bins
#define SCAN_BS 1024
#define SCAN_NBLK ((NB + SCAN_BS - 1) / SCAN_BS)  // 157

// gemm1 tiling: 64 rows per tile, 313 tiles per graph, 2504 total
#define G1_PER_G 313
#define G1_TOT (G1_PER_G * NG)         // 2504
#define DEG_BLOCKS ((TOT_EDGES + 255) / 256)   // 5547
#define S1_TILES 256                   // gemm1 tiles carried by degree launch
#define S2_OFF   S1_TILES
#define S2_TILES (G1_TOT - S1_TILES)   // rest carried by fill launch

// -------- packed f32x2 helpers (sm_100a) --------
typedef unsigned long long u64t;
__device__ __forceinline__ u64t pk2(float lo, float hi) {
    u64t r;
    asm("mov.b64 %0, {%1, %2};" : "=l"(r) : "r"(__float_as_uint(lo)), "r"(__float_as_uint(hi)));
    return r;
}
__device__ __forceinline__ u64t fma2(u64t a, u64t b, u64t c) {
    u64t d;
    asm("fma.rn.f32x2 %0, %1, %2, %3;" : "=l"(d) : "l"(a), "l"(b), "l"(c));
    return d;
}
__device__ __forceinline__ float2 upk2(u64t v) {
    unsigned int lo, hi;
    asm("mov.b64 {%0, %1}, %2;" : "=r"(lo), "=r"(hi) : "l"(v));
    return make_float2(__uint_as_float(lo), __uint_as_float(hi));
}

// -------- scratch (device globals; no allocation allowed) --------
__device__ float g_xw1[NG * N_NODES * H1];
__device__ float g_xw2[NG * N_NODES * H2];
__device__ float g_emb[NG * N_NODES * H2];
__device__ int   g_deg[NB];
__device__ float g_dis[NB];
__device__ int   g_off[NB + 1];
__device__ int   g_cur[NB];
__device__ int   g_csr[TOT_EDGES];
__device__ int   g_bsum[SCAN_NBLK];

// emb_all row k -> slot in g_emb (slot0=sl, 1..7 = ppi,reactome,corum,go_f,go_c,go_p,kegg)
__constant__ int c_slot[14] = {0, 2, 0, 7, 0, 4, 0, 3, 0, 5, 0, 6, 0, 1};

__device__ __forceinline__ void decode_edge(int eid, const int* __restrict__ sl_pos,
                                            const int* __restrict__ kg_edges,
                                            int& g, int& src, int& dst) {
    if (eid < SL_E) {
        g = 0;
        src = sl_pos[eid];
        dst = sl_pos[SL_E + eid];
    } else {
        int r = eid - SL_E;
        int gg = r / KG_E;
        int i = r - gg * KG_E;
        g = gg + 1;
        const int* base = kg_edges + gg * 2 * KG_E;
        src = base[i];
        dst = base[KG_E + i];
    }
}

// -------- gemm1 tile body: 64x128, double-buffered, A pre-duplicated as {a,a} u64 --------
#define A_STRIDE 66   // u64 stride: 528B = 16B-aligned rows, conflict-spread
__device__ void gemm1_tile(const float* __restrict__ x,
                           const float* __restrict__ Wsl1,
                           const float* __restrict__ Wkg1, int tile) {
    __shared__ u64t As2d[2][16 * A_STRIDE];   // [buf][k*66 + row], value = {a,a}
    __shared__ float Bs[2][16][128];          // [buf][k][col]
    int g = tile / G1_PER_G;
    int row0 = (tile - g * G1_PER_G) * 64;
    const float* B = (g == 0) ? Wsl1 : (Wkg1 + (g - 1) * D_IN * H1);
    int t = threadIdx.x;
    int tx = t & 31, ty = t >> 5;
    int ty8 = ty << 3;
    u64t acc2[8][2];
#pragma unroll
    for (int r = 0; r < 8; r++) {
        acc2[r][0] = 0ull;
        acc2[r][1] = 0ull;
    }
    int ai = t >> 2, aq = (t & 3) << 2;
    int arow = row0 + ai;
    int bk0 = t >> 5, bq0 = (t & 31) << 2;   // B row pair: bk0 and bk0+8

    // preload k-block 0
    {
        float4 av = make_float4(0.f, 0.f, 0.f, 0.f);
        if (arow < N_NODES) av = *(const float4*)&x[arow * D_IN + aq];
        As2d[0][(aq + 0) * A_STRIDE + ai] = pk2(av.x, av.x);
        As2d[0][(aq + 1) * A_STRIDE + ai] = pk2(av.y, av.y);
        As2d[0][(aq + 2) * A_STRIDE + ai] = pk2(av.z, av.z);
        As2d[0][(aq + 3) * A_STRIDE + ai] = pk2(av.w, av.w);
        *(float4*)&Bs[0][bk0][bq0] = *(const float4*)&B[bk0 * H1 + bq0];
        *(float4*)&Bs[0][bk0 + 8][bq0] = *(const float4*)&B[(bk0 + 8) * H1 + bq0];
    }
    __syncthreads();

    for (int kb16 = 0; kb16 < 16; kb16++) {
        int cur = kb16 & 1;
        // prefetch next k-block into registers (overlaps with compute below)
        float4 na = make_float4(0.f, 0.f, 0.f, 0.f), nb0, nb1;
        if (kb16 < 15) {
            int kb = (kb16 + 1) * 16;
            if (arow < N_NODES) na = *(const float4*)&x[arow * D_IN + kb + aq];
            nb0 = *(const float4*)&B[(kb + bk0) * H1 + bq0];
            nb1 = *(const float4*)&B[(kb + bk0 + 8) * H1 + bq0];
        }
#pragma unroll
        for (int k = 0; k < 16; k++) {
            // A: 4 broadcast LDS.128, each yields two {a,a} u64 operands
            const ulonglong2* ap = (const ulonglong2*)&As2d[cur][k * A_STRIDE + ty8];
            ulonglong2 a01 = ap[0];
            ulonglong2 a23 = ap[1];
            ulonglong2 a45 = ap[2];
            ulonglong2 a67 = ap[3];
            // B: one LDS.128 read as two packed u64s (consecutive floats)
            ulonglong2 bv = *(const ulonglong2*)&Bs[cur][k][tx << 2];
            u64t b01 = bv.x, b23 = bv.y;
            acc2[0][0] = fma2(a01.x, b01, acc2[0][0]);
            acc2[0][1] = fma2(a01.x, b23, acc2[0][1]);
            acc2[1][0] = fma2(a01.y, b01, acc2[1][0]);
            acc2[1][1] = fma2(a01.y, b23, acc2[1][1]);
            acc2[2][0] = fma2(a23.x, b01, acc2[2][0]);
            acc2[2][1] = fma2(a23.x, b23, acc2[2][1]);
            acc2[3][0] = fma2(a23.y, b01, acc2[3][0]);
            acc2[3][1] = fma2(a23.y, b23, acc2[3][1]);
            acc2[4][0] = fma2(a45.x, b01, acc2[4][0]);
            acc2[4][1] = fma2(a45.x, b23, acc2[4][1]);
            acc2[5][0] = fma2(a45.y, b01, acc2[5][0]);
            acc2[5][1] = fma2(a45.y, b23, acc2[5][1]);
            acc2[6][0] = fma2(a67.x, b01, acc2[6][0]);
            acc2[6][1] = fma2(a67.x, b23, acc2[6][1]);
            acc2[7][0] = fma2(a67.y, b01, acc2[7][0]);
            acc2[7][1] = fma2(a67.y, b23, acc2[7][1]);
        }
        if (kb16 < 15) {
            int nxt = cur ^ 1;
            As2d[nxt][(aq + 0) * A_STRIDE + ai] = pk2(na.x, na.x);
            As2d[nxt][(aq + 1) * A_STRIDE + ai] = pk2(na.y, na.y);
            As2d[nxt][(aq + 2) * A_STRIDE + ai] = pk2(na.z, na.z);
            As2d[nxt][(aq + 3) * A_STRIDE + ai] = pk2(na.w, na.w);
            *(float4*)&Bs[nxt][bk0][bq0] = nb0;
            *(float4*)&Bs[nxt][bk0 + 8][bq0] = nb1;
        }
        __syncthreads();
    }
#pragma unroll
    for (int r = 0; r < 8; r++) {
        int row = row0 + ty8 + r;
        if (row < N_NODES) {
            float2 lo = upk2(acc2[r][0]);
            float2 hi = upk2(acc2[r][1]);
            *(float4*)&g_xw1[(g * N_NODES + row) * H1 + (tx << 2)] =
                make_float4(lo.x, lo.y, hi.x, hi.y);
        }
    }
}

// -------- K1: degree histogram blocks + gemm1 slice 1 --------
__global__ __launch_bounds__(256)
void deg_gemm1_kernel(const float* __restrict__ x,
                      const float* __restrict__ Wsl1, const float* __restrict__ Wkg1,
                      const int* __restrict__ sl_pos, const int* __restrict__ kg_edges) {
    if (blockIdx.x < DEG_BLOCKS) {
        int e = blockIdx.x * 256 + threadIdx.x;
        if (e >= TOT_EDGES) return;
        int g, dst;
        if (e < SL_E) {
            g = 0;
            dst = sl_pos[SL_E + e];
        } else {
            int r = e - SL_E;
            int gg = r / KG_E;
            int i = r - gg * KG_E;
            g = gg + 1;
            dst = kg_edges[gg * 2 * KG_E + KG_E + i];
        }
        atomicAdd(&g_deg[g * N_NODES + dst], 1);
    } else {
        gemm1_tile(x, Wsl1, Wkg1, blockIdx.x - DEG_BLOCKS);
    }
}

// -------- exclusive scan of g_deg -> g_off (also emits g_dis) --------
__global__ void scan_local_kernel() {
    __shared__ int wsum[32];
    int i = blockIdx.x * SCAN_BS + threadIdx.x;
    int lane = threadIdx.x & 31, wid = threadIdx.x >> 5;
    int v = (i < NB) ? g_deg[i] : 0;
    if (i < NB) g_dis[i] = rsqrtf((float)(v + 1));
    int x = v;
#pragma unroll
    for (int d = 1; d < 32; d <<= 1) {
        int y = __shfl_up_sync(0xffffffffu, x, d);
        if (lane >= d) x += y;
    }
    if (lane == 31) wsum[wid] = x;
    __syncthreads();
    if (wid == 0) {
        int s = wsum[lane];
        int t2 = s;
#pragma unroll
        for (int d = 1; d < 32; d <<= 1) {
            int y = __shfl_up_sync(0xffffffffu, t2, d);
            if (lane >= d) t2 += y;
        }
        wsum[lane] = t2 - s;
        if (lane == 31) g_bsum[blockIdx.x] = t2;
    }
    __syncthreads();
    if (i < NB) g_off[i] = x - v + wsum[wid];
}

// top-scan (block-redundant) + add, fused
__global__ void scan_finish_kernel() {
    __shared__ int bs[SCAN_NBLK];
    __shared__ int base;
    int tid = threadIdx.x;
    if (tid < SCAN_NBLK) bs[tid] = g_bsum[tid];
    __syncthreads();
    if (tid == 0) {
        int acc = 0;
        for (int k = 0; k < (int)blockIdx.x; k++) acc += bs[k];
        base = acc;
    }
    __syncthreads();
    int i = blockIdx.x * SCAN_BS + tid;
    if (i < NB) {
        int o = g_off[i] + base;
        g_off[i] = o;
        g_cur[i] = o;
        if (i == NB - 1) g_off[NB] = o + g_deg[i];
    }
}

// -------- K3: CSR fill blocks + ALL remaining gemm1 tiles --------
__global__ __launch_bounds__(256)
void fill_gemm1_kernel(const float* __restrict__ x,
                       const float* __restrict__ Wsl1, const float* __restrict__ Wkg1,
                       const int* __restrict__ sl_pos, const int* __restrict__ kg_edges) {
    if (blockIdx.x < DEG_BLOCKS) {
        int e = blockIdx.x * 256 + threadIdx.x;
        if (e >= TOT_EDGES) return;
        int g, src, dst;
        decode_edge(e, sl_pos, kg_edges, g, src, dst);
        int pos = atomicAdd(&g_cur[g * N_NODES + dst], 1);
        g_csr[pos] = src;
    } else {
        gemm1_tile(x, Wsl1, Wkg1, S2_OFF + blockIdx.x - DEG_BLOCKS);
    }
}

// -------- fused gather1+gemm2: warp gathers h[128], block computes h@W2 --------
__global__ __launch_bounds__(256)
void gcn2_kernel(const float* __restrict__ Wsl2, const float* __restrict__ Wkg2,
                 const float* __restrict__ bsl1, const float* __restrict__ bkg1) {
    __shared__ float hsm[8][132];   // padded: rows differ by 4 banks
    __shared__ float w2s[H1 * H2];
    int g = blockIdx.y;
    const float* W2 = (g == 0) ? Wsl2 : (Wkg2 + (g - 1) * H1 * H2);
    const float* b1 = (g == 0) ? bsl1 : (bkg1 + (g - 1) * H1);
    int t = threadIdx.x;
    int wid = t >> 5, lane = t & 31;
    for (int i = t; i < 512; i += 256)
        ((float4*)w2s)[i] = ((const float4*)W2)[i];

    int node = blockIdx.x * 8 + wid;          // 2500*8 == N_NODES exactly
    int bin = g * N_NODES + node;
    int beg = g_off[bin], end = g_off[bin + 1];
    float disd = g_dis[bin];
    int gbase = g * N_NODES;
    float4 acc = make_float4(0.f, 0.f, 0.f, 0.f);
    int j = beg;
    for (; j + 1 < end; j += 2) {
        int s0 = g_csr[j], s1 = g_csr[j + 1];
        float n0 = disd * g_dis[gbase + s0];
        float n1 = disd * g_dis[gbase + s1];
        const float4 v0 = *(const float4*)&g_xw1[(gbase + s0) * H1 + (lane << 2)];
        const float4 v1 = *(const float4*)&g_xw1[(gbase + s1) * H1 + (lane << 2)];
        acc.x += n0 * v0.x + n1 * v1.x;
        acc.y += n0 * v0.y + n1 * v1.y;
        acc.z += n0 * v0.z + n1 * v1.z;
        acc.w += n0 * v0.w + n1 * v1.w;
    }
    if (j < end) {
        int s0 = g_csr[j];
        float n0 = disd * g_dis[gbase + s0];
        const float4 v0 = *(const float4*)&g_xw1[(gbase + s0) * H1 + (lane << 2)];
        acc.x += n0 * v0.x;
        acc.y += n0 * v0.y;
        acc.z += n0 * v0.z;
        acc.w += n0 * v0.w;
    }
    float ds2 = disd * disd;
    const float4 vs = *(const float4*)&g_xw1[bin * H1 + (lane << 2)];
    const float4 bv = *(const float4*)&b1[lane << 2];
    float4 h;
    h.x = fmaxf(acc.x + ds2 * vs.x + bv.x, 0.f);
    h.y = fmaxf(acc.y + ds2 * vs.y + bv.y, 0.f);
    h.z = fmaxf(acc.z + ds2 * vs.z + bv.z, 0.f);
    h.w = fmaxf(acc.w + ds2 * vs.w + bv.w, 0.f);
    *(float4*)&hsm[wid][lane << 2] = h;
    __syncthreads();

    if (t < 128) {
        int n = t >> 4, jj = t & 15;
        float a = 0.f;
#pragma unroll 8
        for (int k = 0; k < H1; k++) a += hsm[n][k] * w2s[k * 16 + jj];
        g_xw2[(g * N_NODES + blockIdx.x * 8 + n) * H2 + jj] = a;
    }
}

// -------- gather2 fused: emb = agg + dis^2*xw2 + b2  (thread per bin) --------
__global__ void gather2_kernel(const float* __restrict__ bsl2, const float* __restrict__ bkg2) {
    int bin = blockIdx.x * blockDim.x + threadIdx.x;
    if (bin >= NB) return;
    int g = bin / N_NODES;
    int beg = g_off[bin], end = g_off[bin + 1];
    float disd = g_dis[bin];
    int gbase = g * N_NODES;
    float4 a0 = make_float4(0.f, 0.f, 0.f, 0.f);
    float4 a1 = a0, a2 = a0, a3 = a0;
    for (int j = beg; j < end; j++) {
        int src = g_csr[j];
        float nrm = disd * g_dis[gbase + src];
        const float4* row = (const float4*)&g_xw2[(gbase + src) * H2];
        float4 v0 = row[0], v1 = row[1], v2 = row[2], v3 = row[3];
        a0.x += nrm * v0.x; a0.y += nrm * v0.y; a0.z += nrm * v0.z; a0.w += nrm * v0.w;
        a1.x += nrm * v1.x; a1.y += nrm * v1.y; a1.z += nrm * v1.z; a1.w += nrm * v1.w;
        a2.x += nrm * v2.x; a2.y += nrm * v2.y; a2.z += nrm * v2.z; a2.w += nrm * v2.w;
        a3.x += nrm * v3.x; a3.y += nrm * v3.y; a3.z += nrm * v3.z; a3.w += nrm * v3.w;
    }
    float ds2 = disd * disd;
    const float4* sr = (const float4*)&g_xw2[bin * H2];
    const float* b2 = (g == 0) ? bsl2 : (bkg2 + (g - 1) * H2);
    const float4* bb = (const float4*)b2;
    float4 s0 = sr[0], s1 = sr[1], s2 = sr[2], s3 = sr[3];
    float4 b0 = bb[0], b1 = bb[1], b2v = bb[2], b3 = bb[3];
    a0.x += ds2 * s0.x + b0.x; a0.y += ds2 * s0.y + b0.y;
    a0.z += ds2 * s0.z + b0.z; a0.w += ds2 * s0.w + b0.w;
    a1.x += ds2 * s1.x + b1.x; a1.y += ds2 * s1.y + b1.y;
    a1.z += ds2 * s1.z + b1.z; a1.w += ds2 * s1.w + b1.w;
    a2.x += ds2 * s2.x + b2v.x; a2.y += ds2 * s2.y + b2v.y;
    a2.z += ds2 * s2.z + b2v.z; a2.w += ds2 * s2.w + b2v.w;
    a3.x += ds2 * s3.x + b3.x; a3.y += ds2 * s3.y + b3.y;
    a3.z += ds2 * s3.z + b3.z; a3.w += ds2 * s3.w + b3.w;
    float4* o = (float4*)&g_emb[bin * H2];
    o[0] = a0; o[1] = a1; o[2] = a2; o[3] = a3;
}

// -------- per-edge CNN: 5 edge slots per 640-thread block, paired-pooled conv2 --------
struct CnnSmem {
    float w2s[32 * 9 * 64];   // 18432 floats
    float l1w[32 * 64];       // 2048
    float w1s[32 * 8];        // 256
    float c1b[32];
    float c2b[64];
    float l1b[32];
    float l2w[32];
    float l2b[4];             // pad: img 16B-aligned
    float img[CNN_SUBS][2 * 14 * 16];       // 448 each
    float pp[CNN_SUBS][32 * 5 * 6 * 2];     // vertical pairs {p[y],p[y+1]}, 1920 each
    float feats[CNN_SUBS][64];
};

#define BARSYNC(id) asm volatile("bar.sync %0, 128;" :: "r"(id) : "memory")

__global__ __launch_bounds__(CNN_THREADS, 1)
void cnn_kernel(const int* __restrict__ sl_pos, const int* __restrict__ sl_neg,
                const float* __restrict__ conv1_w, const float* __restrict__ conv1_b,
                const float* __restrict__ conv2_w, const float* __restrict__ conv2_b,
                const float* __restrict__ lin1_w, const float* __restrict__ lin1_b,
                const float* __restrict__ lin2_w, const float* __restrict__ lin2_b,
                float* __restrict__ out) {
    extern __shared__ __align__(16) char smem_raw[];
    CnnSmem* s = reinterpret_cast<CnnSmem*>(smem_raw);
    int t = threadIdx.x;
    int sub = t >> 7;       // edge slot 0..4
    int wt = t & 127;       // thread within sub
    int barid = sub + 1;    // named barrier per sub

    // ---- load all weights once per block ----
    for (int i = t; i < 64 * 32 * 9; i += CNN_THREADS) {
        int o = i / 288;
        int rem = i - o * 288;  // c*9 + k
        s->w2s[rem * 64 + o] = conv2_w[i];
    }
    for (int i = t; i < 32 * 64; i += CNN_THREADS) s->l1w[i] = lin1_w[i];
    if (t < 256) s->w1s[t] = conv1_w[t];
    if (t < 32) s->c1b[t] = conv1_b[t];
    if (t < 64) s->c2b[t] = conv2_b[t];
    if (t >= 64 && t < 96) s->l1b[t - 64] = lin1_b[t - 64];
    if (t >= 96 && t < 128) s->l2w[t - 96] = lin2_w[t - 96];
    if (t == 128) s->l2b[0] = lin2_b[0];
    __syncthreads();

    // E_CNN % CNN_SUBS == 0 and base % CNN_SUBS == 0 => e = base+sub < E_CNN always
    for (int base = blockIdx.x * CNN_SUBS; base < E_CNN; base += gridDim.x * CNN_SUBS) {
        int e = base + sub;
        int n0, n1;
        if (e < SL_E) {
            n0 = sl_pos[e];
            n1 = sl_pos[SL_E + e];
        } else {
            n0 = sl_neg[e - SL_E];
            n1 = sl_neg[e];
        }

        // ---- phase 1: gather image [2][14][16] via float4 ----
        if (wt < 112) {
            int c = wt / 56;
            int rem = wt - c * 56;
            int k = rem >> 2;
            int q = (rem & 3) << 2;
            int node = c ? n1 : n0;
            float4 v = *(const float4*)&g_emb[(c_slot[k] * N_NODES + node) * H2 + q];
            *(float4*)&s->img[sub][c * 224 + k * 16 + q] = v;
        }
        BARSYNC(barid);

        // ---- phase 2: conv1 + maxpool -> vertical-pair array pp [c][yp][x][2] ----
        const float* img = s->img[sub];
        float* ppf = s->pp[sub];
        for (int idx = wt; idx < 32 * 6 * 6; idx += 128) {
            int o = idx / 36;
            int rem = idx - o * 36;
            int y = rem / 6;
            int xx = rem - y * 6;
            const float* wv = &s->w1s[o * 8];
            float w0 = wv[0], w1 = wv[1], w2 = wv[2], w3 = wv[3];
            float w4 = wv[4], w5 = wv[5], w6 = wv[6], w7 = wv[7];
            float bb = s->c1b[o];
            float m = -1e30f;
#pragma unroll
            for (int ii = 0; ii < 2; ii++) {
#pragma unroll
                for (int jj = 0; jj < 2; jj++) {
                    int i = 2 * y + ii, j = 2 * xx + jj;
                    const float* i0p = &img[i * 16 + j];
                    const float* i1p = &img[224 + i * 16 + j];
                    float v = bb + w0 * i0p[0] + w1 * i0p[1] + w2 * i0p[16] + w3 * i0p[17] +
                              w4 * i1p[0] + w5 * i1p[1] + w6 * i1p[16] + w7 * i1p[17];
                    m = fmaxf(m, v);
                }
            }
            int pbase = (o * 5) * 6 + xx;
            if (y < 5) ppf[(pbase + y * 6) * 2] = m;
            if (y > 0) ppf[(pbase + (y - 1) * 6) * 2 + 1] = m;
        }
        BARSYNC(barid);

        // ---- phase 3: conv2 (f32x2 on prepacked vertical pairs) + pair-max shfl ----
        {
            int o = wt >> 1, half = wt & 1, i0 = half * 2;
            float bb = s->c2b[o];
            u64t acc2[4];
            u64t bb2 = pk2(bb, bb);
#pragma unroll
            for (int j = 0; j < 4; j++) acc2[j] = bb2;
            const u64t* pp = (const u64t*)s->pp[sub];   // [c][yp][x]
            for (int c = 0; c < 32; c++) {
                const u64t* pc = &pp[c * 30 + i0 * 6];
                const float* wp = &s->w2s[c * 9 * 64 + o];
#pragma unroll
                for (int di = 0; di < 3; di++) {
                    u64t pr0 = pc[di * 6 + 0], pr1 = pc[di * 6 + 1], pr2 = pc[di * 6 + 2];
                    u64t pr3 = pc[di * 6 + 3], pr4 = pc[di * 6 + 4], pr5 = pc[di * 6 + 5];
                    u64t prv[6] = {pr0, pr1, pr2, pr3, pr4, pr5};
#pragma unroll
                    for (int dj = 0; dj < 3; dj++) {
                        float w = wp[(di * 3 + dj) * 64];
                        u64t ww = pk2(w, w);
#pragma unroll
                        for (int j = 0; j < 4; j++)
                            acc2[j] = fma2(prv[dj + j], ww, acc2[j]);
                    }
                }
            }
            float m = -1e30f;
#pragma unroll
            for (int j = 0; j < 4; j++) {
                float2 f = upk2(acc2[j]);
                m = fmaxf(m, fmaxf(f.x, f.y));
            }
            float mo = fmaxf(m, __shfl_down_sync(0xffffffffu, m, 1));
            if ((wt & 1) == 0) s->feats[sub][o] = mo;
        }
        BARSYNC(barid);

        // ---- epilogue: warp 0 of sub (overlaps other warps' next gather) ----
        if (wt < 32) {
            float acc = s->l1b[wt];
            const float* fp = s->feats[sub];
#pragma unroll 16
            for (int d = 0; d < 64; d++) acc += fp[d] * s->l1w[wt * 64 + d];
            float h = fmaxf(acc, 0.f);
            float p = h * s->l2w[wt];
#pragma unroll
            for (int off = 16; off; off >>= 1) p += __shfl_down_sync(0xffffffffu, p, off);
            if (wt == 0) out[e] = 1.f / (1.f + expf(-(p + s->l2b[0])));
        }
        // no trailing barrier: feats[sub] is rewritten only after the NEXT
        // phase-3, which every warp reaches only after two more BARSYNCs.
    }
}

// -------- launch --------
extern "C" void kernel_launch(void* const* d_in, const int* in_sizes, int n_in,
                              void* d_out, int out_size) {
    const float* x       = (const float*)d_in[0];
    const int*   sl_pos  = (const int*)d_in[1];
    const int*   sl_neg  = (const int*)d_in[2];
    const int*   kg_edges= (const int*)d_in[3];
    const float* Wsl1    = (const float*)d_in[4];
    const float* bsl1    = (const float*)d_in[5];
    const float* Wsl2    = (const float*)d_in[6];
    const float* bsl2    = (const float*)d_in[7];
    const float* Wkg1    = (const float*)d_in[8];
    const float* bkg1    = (const float*)d_in[9];
    const float* Wkg2    = (const float*)d_in[10];
    const float* bkg2    = (const float*)d_in[11];
    const float* conv1_w = (const float*)d_in[12];
    const float* conv1_b = (const float*)d_in[13];
    const float* conv2_w = (const float*)d_in[14];
    const float* conv2_b = (const float*)d_in[15];
    const float* lin1_w  = (const float*)d_in[16];
    const float* lin1_b  = (const float*)d_in[17];
    const float* lin2_w  = (const float*)d_in[18];
    const float* lin2_b  = (const float*)d_in[19];
    float* out = (float*)d_out;

    void* p_deg;
    cudaGetSymbolAddress(&p_deg, g_deg);
    cudaMemsetAsync(p_deg, 0, sizeof(int) * NB);

    deg_gemm1_kernel<<<DEG_BLOCKS + S1_TILES, 256>>>(x, Wsl1, Wkg1, sl_pos, kg_edges);
    scan_local_kernel<<<SCAN_NBLK, SCAN_BS>>>();
    scan_finish_kernel<<<SCAN_NBLK, SCAN_BS>>>();
    fill_gemm1_kernel<<<DEG_BLOCKS + S2_TILES, 256>>>(x, Wsl1, Wkg1, sl_pos, kg_edges);
    gcn2_kernel<<<dim3(2500, NG), 256>>>(Wsl2, Wkg2, bsl1, bkg1);
    gather2_kernel<<<(NB + 255) / 256, 256>>>(bsl2, bkg2);

    cudaFuncSetAttribute(cnn_kernel, cudaFuncAttributeMaxDynamicSharedMemorySize,
                         (int)sizeof(CnnSmem));
    cnn_kernel<<<148, CNN_THREADS, sizeof(CnnSmem)>>>(
        sl_pos, sl_neg, conv1_w, conv1_b, conv2_w, conv2_b,
        lin1_w, lin1_b, lin2_w, lin2_b, out);
}

// round 15
// speedup vs baseline: 1.0156x; 1.0156x over previous
#include <cuda_runtime.h>
#include <math.h>

#define N_NODES 20000
#define D_IN 256
#define H1 128
#define H2 16
#define KG_E 200000
#define SL_E 20000
#define NG 8
#define TOT_EDGES (SL_E + 7 * KG_E)
#define E_CNN 40000
#define CNN_SUBS 5
#define CNN_THREADS (128 * CNN_SUBS)   // 640
#define NB (NG * N_NODES)              // 160000 bins
#define SCAN_BS 1024
#define SCAN_NBLK ((NB + SCAN_BS - 1) / SCAN_BS)  // 157

// gemm1 tiling: 128 rows per tile, 157 tiles per graph, 1256 total
#define G1_ROWS 128
#define G1_PER_G 157
#define G1_TOT (G1_PER_G * NG)         // 1256
#define DEG_BLOCKS ((TOT_EDGES + 255) / 256)   // 5547
#define S1_TILES 128                   // gemm1 tiles carried by degree launch
#define S2_OFF   S1_TILES
#define S2_TILES (G1_TOT - S1_TILES)   // 1128, carried by fill launch

// -------- packed f32x2 helpers (sm_100a) --------
typedef unsigned long long u64t;
__device__ __forceinline__ u64t pk2(float lo, float hi) {
    u64t r;
    asm("mov.b64 %0, {%1, %2};" : "=l"(r) : "r"(__float_as_uint(lo)), "r"(__float_as_uint(hi)));
    return r;
}
__device__ __forceinline__ u64t fma2(u64t a, u64t b, u64t c) {
    u64t d;
    asm("fma.rn.f32x2 %0, %1, %2, %3;" : "=l"(d) : "l"(a), "l"(b), "l"(c));
    return d;
}
__device__ __forceinline__ float2 upk2(u64t v) {
    unsigned int lo, hi;
    asm("mov.b64 {%0, %1}, %2;" : "=r"(lo), "=r"(hi) : "l"(v));
    return make_float2(__uint_as_float(lo), __uint_as_float(hi));
}

// -------- scratch (device globals; no allocation allowed) --------
__device__ float g_xw1[NG * N_NODES * H1];
__device__ float g_xw2[NG * N_NODES * H2];
__device__ float g_emb[NG * N_NODES * H2];
__device__ int   g_deg[NB];
__device__ float g_dis[NB];
__device__ int   g_off[NB + 1];
__device__ int   g_cur[NB];
__device__ int   g_csr[TOT_EDGES];
__device__ int   g_bsum[SCAN_NBLK];

// emb_all row k -> slot in g_emb (slot0=sl, 1..7 = ppi,reactome,corum,go_f,go_c,go_p,kegg)
__constant__ int c_slot[14] = {0, 2, 0, 7, 0, 4, 0, 3, 0, 5, 0, 6, 0, 1};

__device__ __forceinline__ void decode_edge(int eid, const int* __restrict__ sl_pos,
                                            const int* __restrict__ kg_edges,
                                            int& g, int& src, int& dst) {
    if (eid < SL_E) {
        g = 0;
        src = sl_pos[eid];
        dst = sl_pos[SL_E + eid];
    } else {
        int r = eid - SL_E;
        int gg = r / KG_E;
        int i = r - gg * KG_E;
        g = gg + 1;
        const int* base = kg_edges + gg * 2 * KG_E;
        src = base[i];
        dst = base[KG_E + i];
    }
}

// -------- gemm1 tile body: 128x128, 8x8 register blocking, double-buffered --------
__device__ void gemm1_tile(const float* __restrict__ x,
                           const float* __restrict__ Wsl1,
                           const float* __restrict__ Wkg1, int tile) {
    __shared__ float As[2][16][G1_ROWS];   // [buf][k][row]
    __shared__ float Bs[2][16][128];       // [buf][k][col]
    int g = tile / G1_PER_G;
    int row0 = (tile - g * G1_PER_G) * G1_ROWS;
    const float* B = (g == 0) ? Wsl1 : (Wkg1 + (g - 1) * D_IN * H1);
    int t = threadIdx.x;
    int tr = t >> 4, tc = t & 15;          // thread -> rows tr*8.., cols tc*8..
    int r8 = tr << 3, c8 = tc << 3;

    u64t acc[8][4];
#pragma unroll
    for (int r = 0; r < 8; r++)
#pragma unroll
        for (int q = 0; q < 4; q++) acc[r][q] = 0ull;

    // load indexing: A chunk = 128 rows x 16 k (512 float4), B chunk = 16 x 128 (512 float4)
    int arow_l = t >> 1;                   // 0..127
    int aq = (t & 1) << 3;                 // 0 or 8 (two float4 = 8 k-values)
    int arow = row0 + arow_l;
    int b_r0 = t >> 5, b_c0 = (t & 31) << 2;   // B rows t>>5 and (t>>5)+8

    // preload k-block 0
    {
        float4 a0 = make_float4(0.f, 0.f, 0.f, 0.f), a1 = a0;
        if (arow < N_NODES) {
            a0 = *(const float4*)&x[arow * D_IN + aq];
            a1 = *(const float4*)&x[arow * D_IN + aq + 4];
        }
        As[0][aq + 0][arow_l] = a0.x;
        As[0][aq + 1][arow_l] = a0.y;
        As[0][aq + 2][arow_l] = a0.z;
        As[0][aq + 3][arow_l] = a0.w;
        As[0][aq + 4][arow_l] = a1.x;
        As[0][aq + 5][arow_l] = a1.y;
        As[0][aq + 6][arow_l] = a1.z;
        As[0][aq + 7][arow_l] = a1.w;
        *(float4*)&Bs[0][b_r0][b_c0] = *(const float4*)&B[b_r0 * H1 + b_c0];
        *(float4*)&Bs[0][b_r0 + 8][b_c0] = *(const float4*)&B[(b_r0 + 8) * H1 + b_c0];
    }
    __syncthreads();

    for (int kb16 = 0; kb16 < 16; kb16++) {
        int cur = kb16 & 1;
        float4 na0 = make_float4(0.f, 0.f, 0.f, 0.f), na1 = na0, nb0, nb1;
        if (kb16 < 15) {
            int kb = (kb16 + 1) * 16;
            if (arow < N_NODES) {
                na0 = *(const float4*)&x[arow * D_IN + kb + aq];
                na1 = *(const float4*)&x[arow * D_IN + kb + aq + 4];
            }
            nb0 = *(const float4*)&B[(kb + b_r0) * H1 + b_c0];
            nb1 = *(const float4*)&B[(kb + b_r0 + 8) * H1 + b_c0];
        }
#pragma unroll
        for (int k = 0; k < 16; k++) {
            float4 alo = *(float4*)&As[cur][k][r8];
            float4 ahi = *(float4*)&As[cur][k][r8 + 4];
            ulonglong2 blo = *(const ulonglong2*)&Bs[cur][k][c8];
            ulonglong2 bhi = *(const ulonglong2*)&Bs[cur][k][c8 + 4];
            u64t b01 = blo.x, b23 = blo.y, b45 = bhi.x, b67 = bhi.y;
            float ar[8] = {alo.x, alo.y, alo.z, alo.w, ahi.x, ahi.y, ahi.z, ahi.w};
#pragma unroll
            for (int r = 0; r < 8; r++) {
                u64t aa = pk2(ar[r], ar[r]);
                acc[r][0] = fma2(aa, b01, acc[r][0]);
                acc[r][1] = fma2(aa, b23, acc[r][1]);
                acc[r][2] = fma2(aa, b45, acc[r][2]);
                acc[r][3] = fma2(aa, b67, acc[r][3]);
            }
        }
        if (kb16 < 15) {
            int nxt = cur ^ 1;
            As[nxt][aq + 0][arow_l] = na0.x;
            As[nxt][aq + 1][arow_l] = na0.y;
            As[nxt][aq + 2][arow_l] = na0.z;
            As[nxt][aq + 3][arow_l] = na0.w;
            As[nxt][aq + 4][arow_l] = na1.x;
            As[nxt][aq + 5][arow_l] = na1.y;
            As[nxt][aq + 6][arow_l] = na1.z;
            As[nxt][aq + 7][arow_l] = na1.w;
            *(float4*)&Bs[nxt][b_r0][b_c0] = nb0;
            *(float4*)&Bs[nxt][b_r0 + 8][b_c0] = nb1;
        }
        __syncthreads();
    }
#pragma unroll
    for (int r = 0; r < 8; r++) {
        int row = row0 + r8 + r;
        if (row < N_NODES) {
            float2 p0 = upk2(acc[r][0]);
            float2 p1 = upk2(acc[r][1]);
            float2 p2 = upk2(acc[r][2]);
            float2 p3 = upk2(acc[r][3]);
            float* o = &g_xw1[(g * N_NODES + row) * H1 + c8];
            *(float4*)&o[0] = make_float4(p0.x, p0.y, p1.x, p1.y);
            *(float4*)&o[4] = make_float4(p2.x, p2.y, p3.x, p3.y);
        }
    }
}

// -------- K1: degree histogram blocks + gemm1 slice 1 --------
__global__ __launch_bounds__(256)
void deg_gemm1_kernel(const float* __restrict__ x,
                      const float* __restrict__ Wsl1, const float* __restrict__ Wkg1,
                      const int* __restrict__ sl_pos, const int* __restrict__ kg_edges) {
    if (blockIdx.x < DEG_BLOCKS) {
        int e = blockIdx.x * 256 + threadIdx.x;
        if (e >= TOT_EDGES) return;
        int g, dst;
        if (e < SL_E) {
            g = 0;
            dst = sl_pos[SL_E + e];
        } else {
            int r = e - SL_E;
            int gg = r / KG_E;
            int i = r - gg * KG_E;
            g = gg + 1;
            dst = kg_edges[gg * 2 * KG_E + KG_E + i];
        }
        atomicAdd(&g_deg[g * N_NODES + dst], 1);
    } else {
        gemm1_tile(x, Wsl1, Wkg1, blockIdx.x - DEG_BLOCKS);
    }
}

// -------- exclusive scan of g_deg -> g_off (also emits g_dis) --------
__global__ void scan_local_kernel() {
    __shared__ int wsum[32];
    int i = blockIdx.x * SCAN_BS + threadIdx.x;
    int lane = threadIdx.x & 31, wid = threadIdx.x >> 5;
    int v = (i < NB) ? g_deg[i] : 0;
    if (i < NB) g_dis[i] = rsqrtf((float)(v + 1));
    int x = v;
#pragma unroll
    for (int d = 1; d < 32; d <<= 1) {
        int y = __shfl_up_sync(0xffffffffu, x, d);
        if (lane >= d) x += y;
    }
    if (lane == 31) wsum[wid] = x;
    __syncthreads();
    if (wid == 0) {
        int s = wsum[lane];
        int t2 = s;
#pragma unroll
        for (int d = 1; d < 32; d <<= 1) {
            int y = __shfl_up_sync(0xffffffffu, t2, d);
            if (lane >= d) t2 += y;
        }
        wsum[lane] = t2 - s;
        if (lane == 31) g_bsum[blockIdx.x] = t2;
    }
    __syncthreads();
    if (i < NB) g_off[i] = x - v + wsum[wid];
}

// top-scan (block-redundant) + add, fused
__global__ void scan_finish_kernel() {
    __shared__ int bs[SCAN_NBLK];
    __shared__ int base;
    int tid = threadIdx.x;
    if (tid < SCAN_NBLK) bs[tid] = g_bsum[tid];
    __syncthreads();
    if (tid == 0) {
        int acc = 0;
        for (int k = 0; k < (int)blockIdx.x; k++) acc += bs[k];
        base = acc;
    }
    __syncthreads();
    int i = blockIdx.x * SCAN_BS + tid;
    if (i < NB) {
        int o = g_off[i] + base;
        g_off[i] = o;
        g_cur[i] = o;
        if (i == NB - 1) g_off[NB] = o + g_deg[i];
    }
}

// -------- K3: CSR fill blocks + ALL remaining gemm1 tiles --------
__global__ __launch_bounds__(256)
void fill_gemm1_kernel(const float* __restrict__ x,
                       const float* __restrict__ Wsl1, const float* __restrict__ Wkg1,
                       const int* __restrict__ sl_pos, const int* __restrict__ kg_edges) {
    if (blockIdx.x < DEG_BLOCKS) {
        int e = blockIdx.x * 256 + threadIdx.x;
        if (e >= TOT_EDGES) return;
        int g, src, dst;
        decode_edge(e, sl_pos, kg_edges, g, src, dst);
        int pos = atomicAdd(&g_cur[g * N_NODES + dst], 1);
        g_csr[pos] = src;
    } else {
        gemm1_tile(x, Wsl1, Wkg1, S2_OFF + blockIdx.x - DEG_BLOCKS);
    }
}

// -------- fused gather1+gemm2: warp gathers h[128], block computes h@W2 --------
__global__ __launch_bounds__(256)
void gcn2_kernel(const float* __restrict__ Wsl2, const float* __restrict__ Wkg2,
                 const float* __restrict__ bsl1, const float* __restrict__ bkg1) {
    __shared__ float hsm[8][132];   // padded: rows differ by 4 banks
    __shared__ float w2s[H1 * H2];
    int g = blockIdx.y;
    const float* W2 = (g == 0) ? Wsl2 : (Wkg2 + (g - 1) * H1 * H2);
    const float* b1 = (g == 0) ? bsl1 : (bkg1 + (g - 1) * H1);
    int t = threadIdx.x;
    int wid = t >> 5, lane = t & 31;
    for (int i = t; i < 512; i += 256)
        ((float4*)w2s)[i] = ((const float4*)W2)[i];

    int node = blockIdx.x * 8 + wid;          // 2500*8 == N_NODES exactly
    int bin = g * N_NODES + node;
    int beg = g_off[bin], end = g_off[bin + 1];
    float disd = g_dis[bin];
    int gbase = g * N_NODES;
    float4 acc = make_float4(0.f, 0.f, 0.f, 0.f);
    int j = beg;
    for (; j + 1 < end; j += 2) {
        int s0 = g_csr[j], s1 = g_csr[j + 1];
        float n0 = disd * g_dis[gbase + s0];
        float n1 = disd * g_dis[gbase + s1];
        const float4 v0 = *(const float4*)&g_xw1[(gbase + s0) * H1 + (lane << 2)];
        const float4 v1 = *(const float4*)&g_xw1[(gbase + s1) * H1 + (lane << 2)];
        acc.x += n0 * v0.x + n1 * v1.x;
        acc.y += n0 * v0.y + n1 * v1.y;
        acc.z += n0 * v0.z + n1 * v1.z;
        acc.w += n0 * v0.w + n1 * v1.w;
    }
    if (j < end) {
        int s0 = g_csr[j];
        float n0 = disd * g_dis[gbase + s0];
        const float4 v0 = *(const float4*)&g_xw1[(gbase + s0) * H1 + (lane << 2)];
        acc.x += n0 * v0.x;
        acc.y += n0 * v0.y;
        acc.z += n0 * v0.z;
        acc.w += n0 * v0.w;
    }
    float ds2 = disd * disd;
    const float4 vs = *(const float4*)&g_xw1[bin * H1 + (lane << 2)];
    const float4 bv = *(const float4*)&b1[lane << 2];
    float4 h;
    h.x = fmaxf(acc.x + ds2 * vs.x + bv.x, 0.f);
    h.y = fmaxf(acc.y + ds2 * vs.y + bv.y, 0.f);
    h.z = fmaxf(acc.z + ds2 * vs.z + bv.z, 0.f);
    h.w = fmaxf(acc.w + ds2 * vs.w + bv.w, 0.f);
    *(float4*)&hsm[wid][lane << 2] = h;
    __syncthreads();

    if (t < 128) {
        int n = t >> 4, jj = t & 15;
        float a = 0.f;
#pragma unroll 8
        for (int k = 0; k < H1; k++) a += hsm[n][k] * w2s[k * 16 + jj];
        g_xw2[(g * N_NODES + blockIdx.x * 8 + n) * H2 + jj] = a;
    }
}

// -------- gather2 fused: emb = agg + dis^2*xw2 + b2  (thread per bin) --------
__global__ void gather2_kernel(const float* __restrict__ bsl2, const float* __restrict__ bkg2) {
    int bin = blockIdx.x * blockDim.x + threadIdx.x;
    if (bin >= NB) return;
    int g = bin / N_NODES;
    int beg = g_off[bin], end = g_off[bin + 1];
    float disd = g_dis[bin];
    int gbase = g * N_NODES;
    float4 a0 = make_float4(0.f, 0.f, 0.f, 0.f);
    float4 a1 = a0, a2 = a0, a3 = a0;
    for (int j = beg; j < end; j++) {
        int src = g_csr[j];
        float nrm = disd * g_dis[gbase + src];
        const float4* row = (const float4*)&g_xw2[(gbase + src) * H2];
        float4 v0 = row[0], v1 = row[1], v2 = row[2], v3 = row[3];
        a0.x += nrm * v0.x; a0.y += nrm * v0.y; a0.z += nrm * v0.z; a0.w += nrm * v0.w;
        a1.x += nrm * v1.x; a1.y += nrm * v1.y; a1.z += nrm * v1.z; a1.w += nrm * v1.w;
        a2.x += nrm * v2.x; a2.y += nrm * v2.y; a2.z += nrm * v2.z; a2.w += nrm * v2.w;
        a3.x += nrm * v3.x; a3.y += nrm * v3.y; a3.z += nrm * v3.z; a3.w += nrm * v3.w;
    }
    float ds2 = disd * disd;
    const float4* sr = (const float4*)&g_xw2[bin * H2];
    const float* b2 = (g == 0) ? bsl2 : (bkg2 + (g - 1) * H2);
    const float4* bb = (const float4*)b2;
    float4 s0 = sr[0], s1 = sr[1], s2 = sr[2], s3 = sr[3];
    float4 b0 = bb[0], b1 = bb[1], b2v = bb[2], b3 = bb[3];
    a0.x += ds2 * s0.x + b0.x; a0.y += ds2 * s0.y + b0.y;
    a0.z += ds2 * s0.z + b0.z; a0.w += ds2 * s0.w + b0.w;
    a1.x += ds2 * s1.x + b1.x; a1.y += ds2 * s1.y + b1.y;
    a1.z += ds2 * s1.z + b1.z; a1.w += ds2 * s1.w + b1.w;
    a2.x += ds2 * s2.x + b2v.x; a2.y += ds2 * s2.y + b2v.y;
    a2.z += ds2 * s2.z + b2v.z; a2.w += ds2 * s2.w + b2v.w;
    a3.x += ds2 * s3.x + b3.x; a3.y += ds2 * s3.y + b3.y;
    a3.z += ds2 * s3.z + b3.z; a3.w += ds2 * s3.w + b3.w;
    float4* o = (float4*)&g_emb[bin * H2];
    o[0] = a0; o[1] = a1; o[2] = a2; o[3] = a3;
}

// -------- per-edge CNN: 5 edge slots per 640-thread block, paired-pooled conv2 --------
struct CnnSmem {
    float w2s[32 * 9 * 64];   // 18432 floats
    float l1w[32 * 64];       // 2048
    float w1s[32 * 8];        // 256
    float c1b[32];
    float c2b[64];
    float l1b[32];
    float l2w[32];
    float l2b[4];             // pad: img 16B-aligned
    float img[CNN_SUBS][2 * 14 * 16];       // 448 each
    float pp[CNN_SUBS][32 * 5 * 6 * 2];     // vertical pairs {p[y],p[y+1]}, 1920 each
    float feats[CNN_SUBS][64];
};

#define BARSYNC(id) asm volatile("bar.sync %0, 128;" :: "r"(id) : "memory")

__global__ __launch_bounds__(CNN_THREADS, 1)
void cnn_kernel(const int* __restrict__ sl_pos, const int* __restrict__ sl_neg,
                const float* __restrict__ conv1_w, const float* __restrict__ conv1_b,
                const float* __restrict__ conv2_w, const float* __restrict__ conv2_b,
                const float* __restrict__ lin1_w, const float* __restrict__ lin1_b,
                const float* __restrict__ lin2_w, const float* __restrict__ lin2_b,
                float* __restrict__ out) {
    extern __shared__ __align__(16) char smem_raw[];
    CnnSmem* s = reinterpret_cast<CnnSmem*>(smem_raw);
    int t = threadIdx.x;
    int sub = t >> 7;       // edge slot 0..4
    int wt = t & 127;       // thread within sub
    int barid = sub + 1;    // named barrier per sub

    // ---- load all weights once per block ----
    for (int i = t; i < 64 * 32 * 9; i += CNN_THREADS) {
        int o = i / 288;
        int rem = i - o * 288;  // c*9 + k
        s->w2s[rem * 64 + o] = conv2_w[i];
    }
    for (int i = t; i < 32 * 64; i += CNN_THREADS) s->l1w[i] = lin1_w[i];
    if (t < 256) s->w1s[t] = conv1_w[t];
    if (t < 32) s->c1b[t] = conv1_b[t];
    if (t < 64) s->c2b[t] = conv2_b[t];
    if (t >= 64 && t < 96) s->l1b[t - 64] = lin1_b[t - 64];
    if (t >= 96 && t < 128) s->l2w[t - 96] = lin2_w[t - 96];
    if (t == 128) s->l2b[0] = lin2_b[0];
    __syncthreads();

    // E_CNN % CNN_SUBS == 0 and base % CNN_SUBS == 0 => e = base+sub < E_CNN always
    for (int base = blockIdx.x * CNN_SUBS; base < E_CNN; base += gridDim.x * CNN_SUBS) {
        int e = base + sub;
        int n0, n1;
        if (e < SL_E) {
            n0 = sl_pos[e];
            n1 = sl_pos[SL_E + e];
        } else {
            n0 = sl_neg[e - SL_E];
            n1 = sl_neg[e];
        }

        // ---- phase 1: gather image [2][14][16] via float4 ----
        if (wt < 112) {
            int c = wt / 56;
            int rem = wt - c * 56;
            int k = rem >> 2;
            int q = (rem & 3) << 2;
            int node = c ? n1 : n0;
            float4 v = *(const float4*)&g_emb[(c_slot[k] * N_NODES + node) * H2 + q];
            *(float4*)&s->img[sub][c * 224 + k * 16 + q] = v;
        }
        BARSYNC(barid);

        // ---- phase 2: conv1 + maxpool -> vertical-pair array pp [c][yp][x][2] ----
        const float* img = s->img[sub];
        float* ppf = s->pp[sub];
        for (int idx = wt; idx < 32 * 6 * 6; idx += 128) {
            int o = idx / 36;
            int rem = idx - o * 36;
            int y = rem / 6;
            int xx = rem - y * 6;
            const float* wv = &s->w1s[o * 8];
            float w0 = wv[0], w1 = wv[1], w2 = wv[2], w3 = wv[3];
            float w4 = wv[4], w5 = wv[5], w6 = wv[6], w7 = wv[7];
            float bb = s->c1b[o];
            float m = -1e30f;
#pragma unroll
            for (int ii = 0; ii < 2; ii++) {
#pragma unroll
                for (int jj = 0; jj < 2; jj++) {
                    int i = 2 * y + ii, j = 2 * xx + jj;
                    const float* i0p = &img[i * 16 + j];
                    const float* i1p = &img[224 + i * 16 + j];
                    float v = bb + w0 * i0p[0] + w1 * i0p[1] + w2 * i0p[16] + w3 * i0p[17] +
                              w4 * i1p[0] + w5 * i1p[1] + w6 * i1p[16] + w7 * i1p[17];
                    m = fmaxf(m, v);
                }
            }
            int pbase = (o * 5) * 6 + xx;
            if (y < 5) ppf[(pbase + y * 6) * 2] = m;
            if (y > 0) ppf[(pbase + (y - 1) * 6) * 2 + 1] = m;
        }
        BARSYNC(barid);

        // ---- phase 3: conv2 (f32x2 on prepacked vertical pairs) + pair-max shfl ----
        {
            int o = wt >> 1, half = wt & 1, i0 = half * 2;
            float bb = s->c2b[o];
            u64t acc2[4];
            u64t bb2 = pk2(bb, bb);
#pragma unroll
            for (int j = 0; j < 4; j++) acc2[j] = bb2;
            const u64t* pp = (const u64t*)s->pp[sub];   // [c][yp][x]
            for (int c = 0; c < 32; c++) {
                const u64t* pc = &pp[c * 30 + i0 * 6];
                const float* wp = &s->w2s[c * 9 * 64 + o];
#pragma unroll
                for (int di = 0; di < 3; di++) {
                    u64t pr0 = pc[di * 6 + 0], pr1 = pc[di * 6 + 1], pr2 = pc[di * 6 + 2];
                    u64t pr3 = pc[di * 6 + 3], pr4 = pc[di * 6 + 4], pr5 = pc[di * 6 + 5];
                    u64t prv[6] = {pr0, pr1, pr2, pr3, pr4, pr5};
#pragma unroll
                    for (int dj = 0; dj < 3; dj++) {
                        float w = wp[(di * 3 + dj) * 64];
                        u64t ww = pk2(w, w);
#pragma unroll
                        for (int j = 0; j < 4; j++)
                            acc2[j] = fma2(prv[dj + j], ww, acc2[j]);
                    }
                }
            }
            float m = -1e30f;
#pragma unroll
            for (int j = 0; j < 4; j++) {
                float2 f = upk2(acc2[j]);
                m = fmaxf(m, fmaxf(f.x, f.y));
            }
            float mo = fmaxf(m, __shfl_down_sync(0xffffffffu, m, 1));
            if ((wt & 1) == 0) s->feats[sub][o] = mo;
        }
        BARSYNC(barid);

        // ---- epilogue: warp 0 of sub (overlaps other warps' next gather) ----
        if (wt < 32) {
            float acc = s->l1b[wt];
            const float* fp = s->feats[sub];
#pragma unroll 16
            for (int d = 0; d < 64; d++) acc += fp[d] * s->l1w[wt * 64 + d];
            float h = fmaxf(acc, 0.f);
            float p = h * s->l2w[wt];
#pragma unroll
            for (int off = 16; off; off >>= 1) p += __shfl_down_sync(0xffffffffu, p, off);
            if (wt == 0) out[e] = 1.f / (1.f + expf(-(p + s->l2b[0])));
        }
        // no trailing barrier: feats[sub] is rewritten only after the NEXT
        // phase-3, which every warp reaches only after two more BARSYNCs.
    }
}

// -------- launch --------
extern "C" void kernel_launch(void* const* d_in, const int* in_sizes, int n_in,
                              void* d_out, int out_size) {
    const float* x       = (const float*)d_in[0];
    const int*   sl_pos  = (const int*)d_in[1];
    const int*   sl_neg  = (const int*)d_in[2];
    const int*   kg_edges= (const int*)d_in[3];
    const float* Wsl1    = (const float*)d_in[4];
    const float* bsl1    = (const float*)d_in[5];
    const float* Wsl2    = (const float*)d_in[6];
    const float* bsl2    = (const float*)d_in[7];
    const float* Wkg1    = (const float*)d_in[8];
    const float* bkg1    = (const float*)d_in[9];
    const float* Wkg2    = (const float*)d_in[10];
    const float* bkg2    = (const float*)d_in[11];
    const float* conv1_w = (const float*)d_in[12];
    const float* conv1_b = (const float*)d_in[13];
    const float* conv2_w = (const float*)d_in[14];
    const float* conv2_b = (const float*)d_in[15];
    const float* lin1_w  = (const float*)d_in[16];
    const float* lin1_b  = (const float*)d_in[17];
    const float* lin2_w  = (const float*)d_in[18];
    const float* lin2_b  = (const float*)d_in[19];
    float* out = (float*)d_out;

    void* p_deg;
    cudaGetSymbolAddress(&p_deg, g_deg);
    cudaMemsetAsync(p_deg, 0, sizeof(int) * NB);

    deg_gemm1_kernel<<<DEG_BLOCKS + S1_TILES, 256>>>(x, Wsl1, Wkg1, sl_pos, kg_edges);
    scan_local_kernel<<<SCAN_NBLK, SCAN_BS>>>();
    scan_finish_kernel<<<SCAN_NBLK, SCAN_BS>>>();
    fill_gemm1_kernel<<<DEG_BLOCKS + S2_TILES, 256>>>(x, Wsl1, Wkg1, sl_pos, kg_edges);
    gcn2_kernel<<<dim3(2500, NG), 256>>>(Wsl2, Wkg2, bsl1, bkg1);
    gather2_kernel<<<(NB + 255) / 256, 256>>>(bsl2, bkg2);

    cudaFuncSetAttribute(cnn_kernel, cudaFuncAttributeMaxDynamicSharedMemorySize,
                         (int)sizeof(CnnSmem));
    cnn_kernel<<<148, CNN_THREADS, sizeof(CnnSmem)>>>(
        sl_pos, sl_neg, conv1_w, conv1_b, conv2_w, conv2_b,
        lin1_w, lin1_b, lin2_w, lin2_b, out);
}

// round 16
// speedup vs baseline: 1.0409x; 1.0250x over previous
#include <cuda_runtime.h>
#include <math.h>

#define N_NODES 20000
#define D_IN 256
#define H1 128
#define H2 16
#define KG_E 200000
#define SL_E 20000
#define NG 8
#define TOT_EDGES (SL_E + 7 * KG_E)
#define E_CNN 40000
#define CNN_SUBS 5
#define CNN_THREADS (128 * CNN_SUBS)   // 640
#define NB (NG * N_NODES)              // 160000 bins
#define SCAN_BS 1024
#define SCAN_NBLK ((NB + SCAN_BS - 1) / SCAN_BS)  // 157

// gemm1 tiling: 64 rows per tile, 313 tiles per graph, 2504 total
#define G1_PER_G 313
#define G1_TOT (G1_PER_G * NG)         // 2504
#define DEG_BLOCKS ((TOT_EDGES + 255) / 256)   // 5547
#define S1_TILES 256                   // gemm1 tiles carried by degree launch
#define S2_OFF   S1_TILES
#define S2_TILES (G1_TOT - S1_TILES)   // rest carried by fill launch

// -------- packed f32x2 helpers (sm_100a) --------
typedef unsigned long long u64t;
__device__ __forceinline__ u64t pk2(float lo, float hi) {
    u64t r;
    asm("mov.b64 %0, {%1, %2};" : "=l"(r) : "r"(__float_as_uint(lo)), "r"(__float_as_uint(hi)));
    return r;
}
__device__ __forceinline__ u64t fma2(u64t a, u64t b, u64t c) {
    u64t d;
    asm("fma.rn.f32x2 %0, %1, %2, %3;" : "=l"(d) : "l"(a), "l"(b), "l"(c));
    return d;
}
__device__ __forceinline__ float2 upk2(u64t v) {
    unsigned int lo, hi;
    asm("mov.b64 {%0, %1}, %2;" : "=r"(lo), "=r"(hi) : "l"(v));
    return make_float2(__uint_as_float(lo), __uint_as_float(hi));
}

// -------- scratch (device globals; no allocation allowed) --------
__device__ float g_xw1[NG * N_NODES * H1];
__device__ float g_xw2[NG * N_NODES * H2];
__device__ float g_emb[NG * N_NODES * H2];
__device__ int   g_deg[NB];
__device__ float g_dis[NB];
__device__ int   g_off[NB + 1];
__device__ int   g_cur[NB];
__device__ int   g_csr[TOT_EDGES];
__device__ int   g_bsum[SCAN_NBLK];

// emb_all row k -> slot in g_emb (slot0=sl, 1..7 = ppi,reactome,corum,go_f,go_c,go_p,kegg)
__constant__ int c_slot[14] = {0, 2, 0, 7, 0, 4, 0, 3, 0, 5, 0, 6, 0, 1};

__device__ __forceinline__ void decode_edge(int eid, const int* __restrict__ sl_pos,
                                            const int* __restrict__ kg_edges,
                                            int& g, int& src, int& dst) {
    if (eid < SL_E) {
        g = 0;
        src = sl_pos[eid];
        dst = sl_pos[SL_E + eid];
    } else {
        int r = eid - SL_E;
        int gg = r / KG_E;
        int i = r - gg * KG_E;
        g = gg + 1;
        const int* base = kg_edges + gg * 2 * KG_E;
        src = base[i];
        dst = base[KG_E + i];
    }
}

// -------- gemm1 tile body: 64x128, double-buffered smem (R13 proven version) --------
__device__ void gemm1_tile(const float* __restrict__ x,
                           const float* __restrict__ Wsl1,
                           const float* __restrict__ Wkg1, int tile) {
    __shared__ float As2[2][16][64];    // [buf][k][row]
    __shared__ float Bs[2][16][128];    // [buf][k][col]
    int g = tile / G1_PER_G;
    int row0 = (tile - g * G1_PER_G) * 64;
    const float* B = (g == 0) ? Wsl1 : (Wkg1 + (g - 1) * D_IN * H1);
    int t = threadIdx.x;
    int tx = t & 31, ty = t >> 5;
    int ty8 = ty << 3;
    u64t acc2[8][2];
#pragma unroll
    for (int r = 0; r < 8; r++) {
        acc2[r][0] = 0ull;
        acc2[r][1] = 0ull;
    }
    int ai = t >> 2, aq = (t & 3) << 2;
    int arow = row0 + ai;
    int bk0 = t >> 5, bq0 = (t & 31) << 2;   // B row pair: bk0 and bk0+8

    // preload k-block 0
    {
        float4 av = make_float4(0.f, 0.f, 0.f, 0.f);
        if (arow < N_NODES) av = *(const float4*)&x[arow * D_IN + aq];
        As2[0][aq + 0][ai] = av.x;
        As2[0][aq + 1][ai] = av.y;
        As2[0][aq + 2][ai] = av.z;
        As2[0][aq + 3][ai] = av.w;
        *(float4*)&Bs[0][bk0][bq0] = *(const float4*)&B[bk0 * H1 + bq0];
        *(float4*)&Bs[0][bk0 + 8][bq0] = *(const float4*)&B[(bk0 + 8) * H1 + bq0];
    }
    __syncthreads();

    for (int kb16 = 0; kb16 < 16; kb16++) {
        int cur = kb16 & 1;
        // prefetch next k-block into registers (overlaps with compute below)
        float4 na = make_float4(0.f, 0.f, 0.f, 0.f), nb0, nb1;
        if (kb16 < 15) {
            int kb = (kb16 + 1) * 16;
            if (arow < N_NODES) na = *(const float4*)&x[arow * D_IN + kb + aq];
            nb0 = *(const float4*)&B[(kb + bk0) * H1 + bq0];
            nb1 = *(const float4*)&B[(kb + bk0 + 8) * H1 + bq0];
        }
#pragma unroll
        for (int k = 0; k < 16; k++) {
            float4 alo = *(float4*)&As2[cur][k][ty8];
            float4 ahi = *(float4*)&As2[cur][k][ty8 + 4];
            float4 b = *(float4*)&Bs[cur][k][tx << 2];
            u64t b01 = pk2(b.x, b.y);
            u64t b23 = pk2(b.z, b.w);
            float ar[8] = {alo.x, alo.y, alo.z, alo.w, ahi.x, ahi.y, ahi.z, ahi.w};
#pragma unroll
            for (int r = 0; r < 8; r++) {
                u64t aa = pk2(ar[r], ar[r]);
                acc2[r][0] = fma2(aa, b01, acc2[r][0]);
                acc2[r][1] = fma2(aa, b23, acc2[r][1]);
            }
        }
        if (kb16 < 15) {
            int nxt = cur ^ 1;
            As2[nxt][aq + 0][ai] = na.x;
            As2[nxt][aq + 1][ai] = na.y;
            As2[nxt][aq + 2][ai] = na.z;
            As2[nxt][aq + 3][ai] = na.w;
            *(float4*)&Bs[nxt][bk0][bq0] = nb0;
            *(float4*)&Bs[nxt][bk0 + 8][bq0] = nb1;
        }
        __syncthreads();
    }
#pragma unroll
    for (int r = 0; r < 8; r++) {
        int row = row0 + ty8 + r;
        if (row < N_NODES) {
            float2 lo = upk2(acc2[r][0]);
            float2 hi = upk2(acc2[r][1]);
            *(float4*)&g_xw1[(g * N_NODES + row) * H1 + (tx << 2)] =
                make_float4(lo.x, lo.y, hi.x, hi.y);
        }
    }
}

// -------- K1: degree histogram blocks + gemm1 slice 1 --------
__global__ __launch_bounds__(256)
void deg_gemm1_kernel(const float* __restrict__ x,
                      const float* __restrict__ Wsl1, const float* __restrict__ Wkg1,
                      const int* __restrict__ sl_pos, const int* __restrict__ kg_edges) {
    if (blockIdx.x < DEG_BLOCKS) {
        int e = blockIdx.x * 256 + threadIdx.x;
        if (e >= TOT_EDGES) return;
        int g, dst;
        if (e < SL_E) {
            g = 0;
            dst = sl_pos[SL_E + e];
        } else {
            int r = e - SL_E;
            int gg = r / KG_E;
            int i = r - gg * KG_E;
            g = gg + 1;
            dst = kg_edges[gg * 2 * KG_E + KG_E + i];
        }
        atomicAdd(&g_deg[g * N_NODES + dst], 1);
    } else {
        gemm1_tile(x, Wsl1, Wkg1, blockIdx.x - DEG_BLOCKS);
    }
}

// -------- exclusive scan of g_deg -> g_off (also emits g_dis) --------
__global__ void scan_local_kernel() {
    __shared__ int wsum[32];
    int i = blockIdx.x * SCAN_BS + threadIdx.x;
    int lane = threadIdx.x & 31, wid = threadIdx.x >> 5;
    int v = (i < NB) ? g_deg[i] : 0;
    if (i < NB) g_dis[i] = rsqrtf((float)(v + 1));
    int x = v;
#pragma unroll
    for (int d = 1; d < 32; d <<= 1) {
        int y = __shfl_up_sync(0xffffffffu, x, d);
        if (lane >= d) x += y;
    }
    if (lane == 31) wsum[wid] = x;
    __syncthreads();
    if (wid == 0) {
        int s = wsum[lane];
        int t2 = s;
#pragma unroll
        for (int d = 1; d < 32; d <<= 1) {
            int y = __shfl_up_sync(0xffffffffu, t2, d);
            if (lane >= d) t2 += y;
        }
        wsum[lane] = t2 - s;
        if (lane == 31) g_bsum[blockIdx.x] = t2;
    }
    __syncthreads();
    if (i < NB) g_off[i] = x - v + wsum[wid];
}

// top-scan (block-redundant) + add, fused
__global__ void scan_finish_kernel() {
    __shared__ int bs[SCAN_NBLK];
    __shared__ int base;
    int tid = threadIdx.x;
    if (tid < SCAN_NBLK) bs[tid] = g_bsum[tid];
    __syncthreads();
    if (tid == 0) {
        int acc = 0;
        for (int k = 0; k < (int)blockIdx.x; k++) acc += bs[k];
        base = acc;
    }
    __syncthreads();
    int i = blockIdx.x * SCAN_BS + tid;
    if (i < NB) {
        int o = g_off[i] + base;
        g_off[i] = o;
        g_cur[i] = o;
        if (i == NB - 1) g_off[NB] = o + g_deg[i];
    }
}

// -------- K3: CSR fill blocks + ALL remaining gemm1 tiles --------
__global__ __launch_bounds__(256)
void fill_gemm1_kernel(const float* __restrict__ x,
                       const float* __restrict__ Wsl1, const float* __restrict__ Wkg1,
                       const int* __restrict__ sl_pos, const int* __restrict__ kg_edges) {
    if (blockIdx.x < DEG_BLOCKS) {
        int e = blockIdx.x * 256 + threadIdx.x;
        if (e >= TOT_EDGES) return;
        int g, src, dst;
        decode_edge(e, sl_pos, kg_edges, g, src, dst);
        int pos = atomicAdd(&g_cur[g * N_NODES + dst], 1);
        g_csr[pos] = src;
    } else {
        gemm1_tile(x, Wsl1, Wkg1, S2_OFF + blockIdx.x - DEG_BLOCKS);
    }
}

// -------- fused gather1+gemm2: warp gathers h[128], block computes h@W2 --------
__global__ __launch_bounds__(256)
void gcn2_kernel(const float* __restrict__ Wsl2, const float* __restrict__ Wkg2,
                 const float* __restrict__ bsl1, const float* __restrict__ bkg1) {
    __shared__ float hsm[8][132];   // padded: rows differ by 4 banks
    __shared__ float w2s[H1 * H2];
    int g = blockIdx.y;
    const float* W2 = (g == 0) ? Wsl2 : (Wkg2 + (g - 1) * H1 * H2);
    const float* b1 = (g == 0) ? bsl1 : (bkg1 + (g - 1) * H1);
    int t = threadIdx.x;
    int wid = t >> 5, lane = t & 31;
    for (int i = t; i < 512; i += 256)
        ((float4*)w2s)[i] = ((const float4*)W2)[i];

    int node = blockIdx.x * 8 + wid;          // 2500*8 == N_NODES exactly
    int bin = g * N_NODES + node;
    int beg = g_off[bin], end = g_off[bin + 1];
    float disd = g_dis[bin];
    int gbase = g * N_NODES;
    float4 acc = make_float4(0.f, 0.f, 0.f, 0.f);
    int j = beg;
    for (; j + 1 < end; j += 2) {
        int s0 = g_csr[j], s1 = g_csr[j + 1];
        float n0 = disd * g_dis[gbase + s0];
        float n1 = disd * g_dis[gbase + s1];
        const float4 v0 = *(const float4*)&g_xw1[(gbase + s0) * H1 + (lane << 2)];
        const float4 v1 = *(const float4*)&g_xw1[(gbase + s1) * H1 + (lane << 2)];
        acc.x += n0 * v0.x + n1 * v1.x;
        acc.y += n0 * v0.y + n1 * v1.y;
        acc.z += n0 * v0.z + n1 * v1.z;
        acc.w += n0 * v0.w + n1 * v1.w;
    }
    if (j < end) {
        int s0 = g_csr[j];
        float n0 = disd * g_dis[gbase + s0];
        const float4 v0 = *(const float4*)&g_xw1[(gbase + s0) * H1 + (lane << 2)];
        acc.x += n0 * v0.x;
        acc.y += n0 * v0.y;
        acc.z += n0 * v0.z;
        acc.w += n0 * v0.w;
    }
    float ds2 = disd * disd;
    const float4 vs = *(const float4*)&g_xw1[bin * H1 + (lane << 2)];
    const float4 bv = *(const float4*)&b1[lane << 2];
    float4 h;
    h.x = fmaxf(acc.x + ds2 * vs.x + bv.x, 0.f);
    h.y = fmaxf(acc.y + ds2 * vs.y + bv.y, 0.f);
    h.z = fmaxf(acc.z + ds2 * vs.z + bv.z, 0.f);
    h.w = fmaxf(acc.w + ds2 * vs.w + bv.w, 0.f);
    *(float4*)&hsm[wid][lane << 2] = h;
    __syncthreads();

    if (t < 128) {
        int n = t >> 4, jj = t & 15;
        float a = 0.f;
#pragma unroll 8
        for (int k = 0; k < H1; k++) a += hsm[n][k] * w2s[k * 16 + jj];
        g_xw2[(g * N_NODES + blockIdx.x * 8 + n) * H2 + jj] = a;
    }
}

// -------- gather2 fused: emb = agg + dis^2*xw2 + b2  (thread per bin) --------
__global__ void gather2_kernel(const float* __restrict__ bsl2, const float* __restrict__ bkg2) {
    int bin = blockIdx.x * blockDim.x + threadIdx.x;
    if (bin >= NB) return;
    int g = bin / N_NODES;
    int beg = g_off[bin], end = g_off[bin + 1];
    float disd = g_dis[bin];
    int gbase = g * N_NODES;
    float4 a0 = make_float4(0.f, 0.f, 0.f, 0.f);
    float4 a1 = a0, a2 = a0, a3 = a0;
    for (int j = beg; j < end; j++) {
        int src = g_csr[j];
        float nrm = disd * g_dis[gbase + src];
        const float4* row = (const float4*)&g_xw2[(gbase + src) * H2];
        float4 v0 = row[0], v1 = row[1], v2 = row[2], v3 = row[3];
        a0.x += nrm * v0.x; a0.y += nrm * v0.y; a0.z += nrm * v0.z; a0.w += nrm * v0.w;
        a1.x += nrm * v1.x; a1.y += nrm * v1.y; a1.z += nrm * v1.z; a1.w += nrm * v1.w;
        a2.x += nrm * v2.x; a2.y += nrm * v2.y; a2.z += nrm * v2.z; a2.w += nrm * v2.w;
        a3.x += nrm * v3.x; a3.y += nrm * v3.y; a3.z += nrm * v3.z; a3.w += nrm * v3.w;
    }
    float ds2 = disd * disd;
    const float4* sr = (const float4*)&g_xw2[bin * H2];
    const float* b2 = (g == 0) ? bsl2 : (bkg2 + (g - 1) * H2);
    const float4* bb = (const float4*)b2;
    float4 s0 = sr[0], s1 = sr[1], s2 = sr[2], s3 = sr[3];
    float4 b0 = bb[0], b1 = bb[1], b2v = bb[2], b3 = bb[3];
    a0.x += ds2 * s0.x + b0.x; a0.y += ds2 * s0.y + b0.y;
    a0.z += ds2 * s0.z + b0.z; a0.w += ds2 * s0.w + b0.w;
    a1.x += ds2 * s1.x + b1.x; a1.y += ds2 * s1.y + b1.y;
    a1.z += ds2 * s1.z + b1.z; a1.w += ds2 * s1.w + b1.w;
    a2.x += ds2 * s2.x + b2v.x; a2.y += ds2 * s2.y + b2v.y;
    a2.z += ds2 * s2.z + b2v.z; a2.w += ds2 * s2.w + b2v.w;
    a3.x += ds2 * s3.x + b3.x; a3.y += ds2 * s3.y + b3.y;
    a3.z += ds2 * s3.z + b3.z; a3.w += ds2 * s3.w + b3.w;
    float4* o = (float4*)&g_emb[bin * H2];
    o[0] = a0; o[1] = a1; o[2] = a2; o[3] = a3;
}

// -------- per-edge CNN: 5 edge slots per 640-thread block, paired-pooled conv2 --------
struct CnnSmem {
    float w2s[32 * 9 * 64];   // 18432 floats
    float l1w[32 * 64];       // 2048
    float w1s[32 * 8];        // 256
    float c1b[32];
    float c2b[64];
    float l1b[32];
    float l2w[32];
    float l2b[4];             // pad: img 16B-aligned
    float img[CNN_SUBS][2 * 14 * 16];       // 448 each
    float pp[CNN_SUBS][32 * 5 * 6 * 2];     // vertical pairs {p[y],p[y+1]}, 1920 each
    float feats[CNN_SUBS][64];
};

#define BARSYNC(id) asm volatile("bar.sync %0, 128;" :: "r"(id) : "memory")

__global__ __launch_bounds__(CNN_THREADS, 1)
void cnn_kernel(const int* __restrict__ sl_pos, const int* __restrict__ sl_neg,
                const float* __restrict__ conv1_w, const float* __restrict__ conv1_b,
                const float* __restrict__ conv2_w, const float* __restrict__ conv2_b,
                const float* __restrict__ lin1_w, const float* __restrict__ lin1_b,
                const float* __restrict__ lin2_w, const float* __restrict__ lin2_b,
                float* __restrict__ out) {
    extern __shared__ __align__(16) char smem_raw[];
    CnnSmem* s = reinterpret_cast<CnnSmem*>(smem_raw);
    int t = threadIdx.x;
    int sub = t >> 7;       // edge slot 0..4
    int wt = t & 127;       // thread within sub
    int barid = sub + 1;    // named barrier per sub

    // ---- load all weights once per block ----
    for (int i = t; i < 64 * 32 * 9; i += CNN_THREADS) {
        int o = i / 288;
        int rem = i - o * 288;  // c*9 + k
        s->w2s[rem * 64 + o] = conv2_w[i];
    }
    for (int i = t; i < 32 * 64; i += CNN_THREADS) s->l1w[i] = lin1_w[i];
    if (t < 256) s->w1s[t] = conv1_w[t];
    if (t < 32) s->c1b[t] = conv1_b[t];
    if (t < 64) s->c2b[t] = conv2_b[t];
    if (t >= 64 && t < 96) s->l1b[t - 64] = lin1_b[t - 64];
    if (t >= 96 && t < 128) s->l2w[t - 96] = lin2_w[t - 96];
    if (t == 128) s->l2b[0] = lin2_b[0];
    __syncthreads();

    // E_CNN % CNN_SUBS == 0 and base % CNN_SUBS == 0 => e = base+sub < E_CNN always
    for (int base = blockIdx.x * CNN_SUBS; base < E_CNN; base += gridDim.x * CNN_SUBS) {
        int e = base + sub;
        int n0, n1;
        if (e < SL_E) {
            n0 = sl_pos[e];
            n1 = sl_pos[SL_E + e];
        } else {
            n0 = sl_neg[e - SL_E];
            n1 = sl_neg[e];
        }

        // ---- phase 1: gather image [2][14][16] via float4 ----
        if (wt < 112) {
            int c = wt / 56;
            int rem = wt - c * 56;
            int k = rem >> 2;
            int q = (rem & 3) << 2;
            int node = c ? n1 : n0;
            float4 v = *(const float4*)&g_emb[(c_slot[k] * N_NODES + node) * H2 + q];
            *(float4*)&s->img[sub][c * 224 + k * 16 + q] = v;
        }
        BARSYNC(barid);

        // ---- phase 2: conv1 + maxpool -> vertical-pair array pp [c][yp][x][2] ----
        const float* img = s->img[sub];
        float* ppf = s->pp[sub];
        for (int idx = wt; idx < 32 * 6 * 6; idx += 128) {
            int o = idx / 36;
            int rem = idx - o * 36;
            int y = rem / 6;
            int xx = rem - y * 6;
            const float* wv = &s->w1s[o * 8];
            float w0 = wv[0], w1 = wv[1], w2 = wv[2], w3 = wv[3];
            float w4 = wv[4], w5 = wv[5], w6 = wv[6], w7 = wv[7];
            float bb = s->c1b[o];
            float m = -1e30f;
#pragma unroll
            for (int ii = 0; ii < 2; ii++) {
#pragma unroll
                for (int jj = 0; jj < 2; jj++) {
                    int i = 2 * y + ii, j = 2 * xx + jj;
                    const float* i0p = &img[i * 16 + j];
                    const float* i1p = &img[224 + i * 16 + j];
                    float v = bb + w0 * i0p[0] + w1 * i0p[1] + w2 * i0p[16] + w3 * i0p[17] +
                              w4 * i1p[0] + w5 * i1p[1] + w6 * i1p[16] + w7 * i1p[17];
                    m = fmaxf(m, v);
                }
            }
            int pbase = (o * 5) * 6 + xx;
            if (y < 5) ppf[(pbase + y * 6) * 2] = m;
            if (y > 0) ppf[(pbase + (y - 1) * 6) * 2 + 1] = m;
        }
        BARSYNC(barid);

        // ---- phase 3: conv2 (f32x2, vectorized LDS.128 pair loads) + pair-max shfl ----
        {
            int o = wt >> 1, half = wt & 1, i0 = half * 2;
            float bb = s->c2b[o];
            u64t acc2[4];
            u64t bb2 = pk2(bb, bb);
#pragma unroll
            for (int j = 0; j < 4; j++) acc2[j] = bb2;
            const u64t* pp = (const u64t*)s->pp[sub];   // [c][yp][x]
            for (int c = 0; c < 32; c++) {
                const u64t* pc = &pp[c * 30 + i0 * 6];
                const float* wp = &s->w2s[c * 9 * 64 + o];
#pragma unroll
                for (int di = 0; di < 3; di++) {
                    // 6 consecutive u64 pairs -> 3 LDS.128 (all offsets 16B-aligned)
                    ulonglong2 p01 = *(const ulonglong2*)&pc[di * 6 + 0];
                    ulonglong2 p23 = *(const ulonglong2*)&pc[di * 6 + 2];
                    ulonglong2 p45 = *(const ulonglong2*)&pc[di * 6 + 4];
                    u64t prv[6] = {p01.x, p01.y, p23.x, p23.y, p45.x, p45.y};
#pragma unroll
                    for (int dj = 0; dj < 3; dj++) {
                        float w = wp[(di * 3 + dj) * 64];
                        u64t ww = pk2(w, w);
#pragma unroll
                        for (int j = 0; j < 4; j++)
                            acc2[j] = fma2(prv[dj + j], ww, acc2[j]);
                    }
                }
            }
            float m = -1e30f;
#pragma unroll
            for (int j = 0; j < 4; j++) {
                float2 f = upk2(acc2[j]);
                m = fmaxf(m, fmaxf(f.x, f.y));
            }
            float mo = fmaxf(m, __shfl_down_sync(0xffffffffu, m, 1));
            if ((wt & 1) == 0) s->feats[sub][o] = mo;
        }
        BARSYNC(barid);

        // ---- epilogue: warp 0 of sub (overlaps other warps' next gather) ----
        if (wt < 32) {
            float acc = s->l1b[wt];
            const float* fp = s->feats[sub];
#pragma unroll 16
            for (int d = 0; d < 64; d++) acc += fp[d] * s->l1w[wt * 64 + d];
            float h = fmaxf(acc, 0.f);
            float p = h * s->l2w[wt];
#pragma unroll
            for (int off = 16; off; off >>= 1) p += __shfl_down_sync(0xffffffffu, p, off);
            if (wt == 0) out[e] = 1.f / (1.f + expf(-(p + s->l2b[0])));
        }
        // no trailing barrier: feats[sub] is rewritten only after the NEXT
        // phase-3, which every warp reaches only after two more BARSYNCs.
    }
}

// -------- launch --------
extern "C" void kernel_launch(void* const* d_in, const int* in_sizes, int n_in,
                              void* d_out, int out_size) {
    const float* x       = (const float*)d_in[0];
    const int*   sl_pos  = (const int*)d_in[1];
    const int*   sl_neg  = (const int*)d_in[2];
    const int*   kg_edges= (const int*)d_in[3];
    const float* Wsl1    = (const float*)d_in[4];
    const float* bsl1    = (const float*)d_in[5];
    const float* Wsl2    = (const float*)d_in[6];
    const float* bsl2    = (const float*)d_in[7];
    const float* Wkg1    = (const float*)d_in[8];
    const float* bkg1    = (const float*)d_in[9];
    const float* Wkg2    = (const float*)d_in[10];
    const float* bkg2    = (const float*)d_in[11];
    const float* conv1_w = (const float*)d_in[12];
    const float* conv1_b = (const float*)d_in[13];
    const float* conv2_w = (const float*)d_in[14];
    const float* conv2_b = (const float*)d_in[15];
    const float* lin1_w  = (const float*)d_in[16];
    const float* lin1_b  = (const float*)d_in[17];
    const float* lin2_w  = (const float*)d_in[18];
    const float* lin2_b  = (const float*)d_in[19];
    float* out = (float*)d_out;

    void* p_deg;
    cudaGetSymbolAddress(&p_deg, g_deg);
    cudaMemsetAsync(p_deg, 0, sizeof(int) * NB);

    deg_gemm1_kernel<<<DEG_BLOCKS + S1_TILES, 256>>>(x, Wsl1, Wkg1, sl_pos, kg_edges);
    scan_local_kernel<<<SCAN_NBLK, SCAN_BS>>>();
    scan_finish_kernel<<<SCAN_NBLK, SCAN_BS>>>();
    fill_gemm1_kernel<<<DEG_BLOCKS + S2_TILES, 256>>>(x, Wsl1, Wkg1, sl_pos, kg_edges);
    gcn2_kernel<<<dim3(2500, NG), 256>>>(Wsl2, Wkg2, bsl1, bkg1);
    gather2_kernel<<<(NB + 255) / 256, 256>>>(bsl2, bkg2);

    cudaFuncSetAttribute(cnn_kernel, cudaFuncAttributeMaxDynamicSharedMemorySize,
                         (int)sizeof(CnnSmem));
    cnn_kernel<<<148, CNN_THREADS, sizeof(CnnSmem)>>>(
        sl_pos, sl_neg, conv1_w, conv1_b, conv2_w, conv2_b,
        lin1_w, lin1_b, lin2_w, lin2_b, out);
}